// round 1
// baseline (speedup 1.0000x reference)
#include <cuda_runtime.h>
#include <math.h>
#include <stdint.h>

#define BATCH 32
#define SEQ   2048
#define HID   512

// Scratch (static device globals: allocation-free)
__device__ float g_xproj[SEQ * BATCH * HID];   // [s][b][h] layout, 128 MB
__device__ float g_h[2][BATCH * HID];          // double-buffered hidden state
__device__ unsigned int g_ctr[8 * (SEQ + 1)]; // per batch-group barrier counters

// ---------------------------------------------------------------------------
// Kernel 0: zero barrier counters (per-launch determinism)
// ---------------------------------------------------------------------------
__global__ void zero_ctr_kernel() {
    int i = blockIdx.x * blockDim.x + threadIdx.x;
    if (i < 8 * (SEQ + 1)) g_ctr[i] = 0u;
}

// ---------------------------------------------------------------------------
// Kernel 1: xproj = x @ W_xh^T + (b_xh + b_hh + b_h), written as [s][b][h]
// Classic 128x128 block / 8x8 thread tile SGEMM. M=65536, N=512, K=512.
// ---------------------------------------------------------------------------
__global__ __launch_bounds__(256) void xproj_gemm(
    const float* __restrict__ X,      // [B][S][512] row-major => M=B*S rows
    const float* __restrict__ Wxh,    // [512][512], out[m][n] = sum_k X[m][k]*Wxh[n][k]
    const float* __restrict__ bxh,
    const float* __restrict__ bhh,
    const float* __restrict__ bh)
{
    __shared__ float As[8][128];
    __shared__ float Bs[8][128];
    const int K = HID;
    const int m0 = blockIdx.x * 128;
    const int n0 = blockIdx.y * 128;
    const int tid = threadIdx.x;

    const int lr = tid >> 1;           // 0..127 row within tile for loads
    const int lc = (tid & 1) << 2;     // 0 or 4

    const int ca = (tid & 15) << 2;    // col base a (0..60 step 4)
    const int ra = (tid >> 4) << 2;    // row base a

    float acc[8][8];
#pragma unroll
    for (int i = 0; i < 8; i++)
#pragma unroll
        for (int j = 0; j < 8; j++) acc[i][j] = 0.f;

    const float* Aptr = X   + (size_t)(m0 + lr) * K + lc;
    const float* Bptr = Wxh + (size_t)(n0 + lr) * K + lc;

    for (int k0 = 0; k0 < K; k0 += 8) {
        float4 a4 = *(const float4*)(Aptr + k0);
        float4 b4 = *(const float4*)(Bptr + k0);
        As[lc + 0][lr] = a4.x; As[lc + 1][lr] = a4.y;
        As[lc + 2][lr] = a4.z; As[lc + 3][lr] = a4.w;
        Bs[lc + 0][lr] = b4.x; Bs[lc + 1][lr] = b4.y;
        Bs[lc + 2][lr] = b4.z; Bs[lc + 3][lr] = b4.w;
        __syncthreads();
#pragma unroll
        for (int k = 0; k < 8; k++) {
            float am[8], bn[8];
            *(float4*)&am[0] = *(const float4*)&As[k][ra];
            *(float4*)&am[4] = *(const float4*)&As[k][ra + 64];
            *(float4*)&bn[0] = *(const float4*)&Bs[k][ca];
            *(float4*)&bn[4] = *(const float4*)&Bs[k][ca + 64];
#pragma unroll
            for (int i = 0; i < 8; i++)
#pragma unroll
                for (int j = 0; j < 8; j++)
                    acc[i][j] = fmaf(am[i], bn[j], acc[i][j]);
        }
        __syncthreads();
    }

    // bias per output column
    float biasv[8];
#pragma unroll
    for (int j = 0; j < 8; j++) {
        int n = n0 + ((j < 4) ? (ca + j) : (64 + ca + j - 4));
        biasv[j] = bxh[n] + bhh[n] + bh[n];
    }

#pragma unroll
    for (int i = 0; i < 8; i++) {
        int m = m0 + ((i < 4) ? (ra + i) : (64 + ra + i - 4));
        int b = m >> 11;          // m / SEQ
        int s = m & (SEQ - 1);    // m % SEQ
        float* outr = &g_xproj[((size_t)s * BATCH + b) * HID + n0];
        float4 v0, v1;
        v0.x = acc[i][0] + biasv[0]; v0.y = acc[i][1] + biasv[1];
        v0.z = acc[i][2] + biasv[2]; v0.w = acc[i][3] + biasv[3];
        v1.x = acc[i][4] + biasv[4]; v1.y = acc[i][5] + biasv[5];
        v1.z = acc[i][6] + biasv[6]; v1.w = acc[i][7] + biasv[7];
        *(float4*)&outr[ca]      = v0;
        *(float4*)&outr[64 + ca] = v1;
    }
}

// ---------------------------------------------------------------------------
// Kernel 2: persistent recurrent scan.
// Grid = 128 CTAs: 8 batch-groups (4 batches each) x 16 hidden-groups (32 i's).
// W_hh slice lives in SMEM transposed [k][i_local] (pad 33 -> conflict-free).
// h exchanged through L2 (ld.cg/st.cg), software barrier per batch-group.
// Inner product uses packed fma.rn.f32x2 (2x fp32 rate on sm_103a).
// ---------------------------------------------------------------------------
__global__ __launch_bounds__(256) void scan_kernel(const float* __restrict__ Whh)
{
    const int bg = blockIdx.x >> 4;    // 0..7
    const int ig = blockIdx.x & 15;    // 0..15
    const int b0 = bg * 4;
    const int i0 = ig * 32;
    const int tid  = threadIdx.x;
    const int lane = tid & 31;
    const int warp = tid >> 5;         // 0..7, each owns a 64-wide K chunk

    extern __shared__ float sm[];
    float* Ws   = sm;                  // [512][33]
    float* hs   = Ws + 512 * 33;       // [512][4]  (k-major, 4 batches)
    float* part = hs + 512 * 4;        // [8][128]  k-split partials

    // Load W_hh rows [i0, i0+32) transposed: Ws[k*33 + il] = Whh[(i0+il)*512 + k]
    for (int idx = tid; idx < 32 * 512; idx += 256) {
        int il = idx >> 9;
        int k  = idx & 511;
        Ws[k * 33 + il] = Whh[(size_t)(i0 + il) * HID + k];
    }

    // Zero our slice of h buffer 0
    if (tid < 128) {
        int b  = tid >> 5;
        int il = tid & 31;
        __stcg(&g_h[0][(b0 + b) * HID + i0 + il], 0.f);
    }
    __threadfence();
    __syncthreads();

    // init barrier (slot 0) across the 16 CTAs of this batch-group
    unsigned int* ctr = &g_ctr[bg * (SEQ + 1)];
    if (tid == 0) {
        atomicAdd(&ctr[0], 1u);
        while (((volatile unsigned int*)ctr)[0] < 16u) {}
    }
    __syncthreads();

    for (int s = 0; s < SEQ; s++) {
        const float* hbuf = g_h[s & 1];
        // stage h (4 batches x 512) transposed into smem: hs[k*4+b]
        for (int idx = tid; idx < 2048; idx += 256) {
            int b = idx & 3;
            int k = idx >> 2;
            hs[idx] = __ldcg(&hbuf[(b0 + b) * HID + k]);
        }
        __syncthreads();

        // each warp: 32 hidden outputs (lane=i_local) x 4 batches over K chunk [warp*64, +64)
        unsigned long long acc01 = 0ull, acc23 = 0ull;  // packed f32x2 pairs (b0,b1) (b2,b3)
        const int kbase = warp * 64;
#pragma unroll 8
        for (int kk = 0; kk < 64; kk++) {
            int k = kbase + kk;
            float wv = Ws[k * 33 + lane];
            unsigned long long wp;
            asm("mov.b64 %0, {%1, %1};" : "=l"(wp) : "f"(wv));
            ulonglong2 hp = *(const ulonglong2*)&hs[k * 4];
            asm("fma.rn.f32x2 %0, %1, %2, %0;" : "+l"(acc01) : "l"(wp), "l"(hp.x));
            asm("fma.rn.f32x2 %0, %1, %2, %0;" : "+l"(acc23) : "l"(wp), "l"(hp.y));
        }
        float a0, a1, a2, a3;
        asm("mov.b64 {%0, %1}, %2;" : "=f"(a0), "=f"(a1) : "l"(acc01));
        asm("mov.b64 {%0, %1}, %2;" : "=f"(a2), "=f"(a3) : "l"(acc23));
        float* pw = &part[warp * 128 + lane * 4];
        pw[0] = a0; pw[1] = a1; pw[2] = a2; pw[3] = a3;
        __syncthreads();

        if (tid < 128) {
            float sum = 0.f;
#pragma unroll
            for (int w = 0; w < 8; w++) sum += part[w * 128 + tid];
            int il = tid >> 2;
            int b  = tid & 3;
            float xp = g_xproj[((size_t)s * BATCH + (b0 + b)) * HID + i0 + il];
            float v = tanhf(xp + sum);
            __stcg(&g_h[(s + 1) & 1][(b0 + b) * HID + i0 + il], v);
        }
        __threadfence();
        __syncthreads();

        if (tid == 0) {
            atomicAdd(&ctr[s + 1], 1u);
            while (((volatile unsigned int*)ctr)[s + 1] < 16u) {}
        }
        __syncthreads();
    }
}

// ---------------------------------------------------------------------------
// Kernel 3: out = h_final @ W_fc^T + b_fc.  h_final lives in g_h[0] (2048 even).
// One block per batch; warp-per-output with shfl reduction.
// ---------------------------------------------------------------------------
__global__ __launch_bounds__(512) void fc_kernel(
    const float* __restrict__ Wfc, const float* __restrict__ bfc,
    float* __restrict__ out)
{
    __shared__ float hsm[HID];
    const int b = blockIdx.x;
    const int tid = threadIdx.x;
    hsm[tid] = g_h[0][b * HID + tid];
    __syncthreads();
    const int warp = tid >> 5;
    const int lane = tid & 31;
#pragma unroll 4
    for (int oi = 0; oi < 32; oi++) {
        int o = warp * 32 + oi;
        const float* wr = Wfc + (size_t)o * HID;
        float sum = 0.f;
#pragma unroll 4
        for (int j = lane; j < HID; j += 32) sum = fmaf(hsm[j], wr[j], sum);
#pragma unroll
        for (int off = 16; off > 0; off >>= 1)
            sum += __shfl_down_sync(0xffffffffu, sum, off);
        if (lane == 0) out[b * HID + o] = sum + bfc[o];
    }
}

// ---------------------------------------------------------------------------
extern "C" void kernel_launch(void* const* d_in, const int* in_sizes, int n_in,
                              void* d_out, int out_size)
{
    const float* x   = (const float*)d_in[0];
    const float* Wxh = (const float*)d_in[1];
    const float* bxh = (const float*)d_in[2];
    const float* Whh = (const float*)d_in[3];
    const float* bhh = (const float*)d_in[4];
    const float* bh  = (const float*)d_in[5];
    const float* Wfc = (const float*)d_in[6];
    const float* bfc = (const float*)d_in[7];
    float* out = (float*)d_out;

    static size_t scan_smem = (512 * 33 + 512 * 4 + 8 * 128) * sizeof(float);
    static bool attr_set = false;
    if (!attr_set) {
        cudaFuncSetAttribute(scan_kernel,
                             cudaFuncAttributeMaxDynamicSharedMemorySize,
                             (int)scan_smem);
        attr_set = true;
    }

    zero_ctr_kernel<<<65, 256>>>();
    xproj_gemm<<<dim3((BATCH * SEQ) / 128, HID / 128), 256>>>(x, Wxh, bxh, bhh, bh);
    scan_kernel<<<128, 256, scan_smem>>>(Whh);
    fc_kernel<<<BATCH, 512>>>(Wfc, bfc, out);
}

// round 2
// speedup vs baseline: 1.3405x; 1.3405x over previous
#include <cuda_runtime.h>
#include <math.h>
#include <stdint.h>

#define BATCH 32
#define SEQ   2048
#define HID   512

typedef unsigned long long ull;

// Scratch (static device globals: allocation-free)
__device__ float g_xproj[SEQ * BATCH * HID];   // [s][b][h] layout
__device__ float g_hfin[BATCH * HID];          // final hidden state

// ---------------------------------------------------------------------------
// packed f32x2 helpers (FFMA2 only reachable via PTX)
// ---------------------------------------------------------------------------
__device__ __forceinline__ void ffma2(ull& acc, ull a, ull b) {
    asm("fma.rn.f32x2 %0, %1, %2, %0;" : "+l"(acc) : "l"(a), "l"(b));
}
__device__ __forceinline__ ull dup2(float v) {
    ull r; asm("mov.b64 %0, {%1, %1};" : "=l"(r) : "f"(v)); return r;
}
__device__ __forceinline__ float2 unpk(ull v) {
    float2 r; asm("mov.b64 {%0, %1}, %2;" : "=f"(r.x), "=f"(r.y) : "l"(v)); return r;
}

// ---------------------------------------------------------------------------
// Kernel 1: xproj = x @ W_xh^T + (b_xh + b_hh + b_h), written as [s][b][h]
// 128x128 block / 8x8 thread tile, inner product via packed FFMA2.
// ---------------------------------------------------------------------------
__global__ __launch_bounds__(256, 2) void xproj_gemm(
    const float* __restrict__ X,
    const float* __restrict__ Wxh,
    const float* __restrict__ bxh,
    const float* __restrict__ bhh,
    const float* __restrict__ bh)
{
    __shared__ float As[8][128];
    __shared__ float Bs[8][128];
    const int K = HID;
    const int m0 = blockIdx.x * 128;
    const int n0 = blockIdx.y * 128;
    const int tid = threadIdx.x;

    const int lr = tid >> 1;
    const int lc = (tid & 1) << 2;
    const int ca = (tid & 15) << 2;
    const int ra = (tid >> 4) << 2;

    ull acc[8][4];
#pragma unroll
    for (int i = 0; i < 8; i++)
#pragma unroll
        for (int j = 0; j < 4; j++) acc[i][j] = 0ull;

    const float* Aptr = X   + (size_t)(m0 + lr) * K + lc;
    const float* Bptr = Wxh + (size_t)(n0 + lr) * K + lc;

    for (int k0 = 0; k0 < K; k0 += 8) {
        float4 a4 = *(const float4*)(Aptr + k0);
        float4 b4 = *(const float4*)(Bptr + k0);
        As[lc + 0][lr] = a4.x; As[lc + 1][lr] = a4.y;
        As[lc + 2][lr] = a4.z; As[lc + 3][lr] = a4.w;
        Bs[lc + 0][lr] = b4.x; Bs[lc + 1][lr] = b4.y;
        Bs[lc + 2][lr] = b4.z; Bs[lc + 3][lr] = b4.w;
        __syncthreads();
#pragma unroll
        for (int k = 0; k < 8; k++) {
            float am[8];
            *(float4*)&am[0] = *(const float4*)&As[k][ra];
            *(float4*)&am[4] = *(const float4*)&As[k][ra + 64];
            ulonglong2 b01 = *(const ulonglong2*)&Bs[k][ca];       // cols ca..ca+3
            ulonglong2 b23 = *(const ulonglong2*)&Bs[k][ca + 64];  // cols 64+ca..
#pragma unroll
            for (int i = 0; i < 8; i++) {
                ull ad = dup2(am[i]);
                ffma2(acc[i][0], ad, b01.x);
                ffma2(acc[i][1], ad, b01.y);
                ffma2(acc[i][2], ad, b23.x);
                ffma2(acc[i][3], ad, b23.y);
            }
        }
        __syncthreads();
    }

    float biasv[8];
#pragma unroll
    for (int j = 0; j < 8; j++) {
        int n = n0 + ((j < 4) ? (ca + j) : (64 + ca + j - 4));
        biasv[j] = bxh[n] + bhh[n] + bh[n];
    }

#pragma unroll
    for (int i = 0; i < 8; i++) {
        int m = m0 + ((i < 4) ? (ra + i) : (64 + ra + i - 4));
        int b = m >> 11;
        int s = m & (SEQ - 1);
        float* outr = &g_xproj[((size_t)s * BATCH + b) * HID + n0];
        float2 p0 = unpk(acc[i][0]);
        float2 p1 = unpk(acc[i][1]);
        float2 p2 = unpk(acc[i][2]);
        float2 p3 = unpk(acc[i][3]);
        float4 v0, v1;
        v0.x = p0.x + biasv[0]; v0.y = p0.y + biasv[1];
        v0.z = p1.x + biasv[2]; v0.w = p1.y + biasv[3];
        v1.x = p2.x + biasv[4]; v1.y = p2.y + biasv[5];
        v1.z = p3.x + biasv[6]; v1.w = p3.y + biasv[7];
        *(float4*)&outr[ca]      = v0;
        *(float4*)&outr[64 + ca] = v1;
    }
}

// ---------------------------------------------------------------------------
// Kernel 2: persistent recurrent scan over CGA clusters.
// 16 clusters x 8 CTAs. Cluster = 2 batches; CTA rank r = hidden rows
// [r*64, r*64+64). Weights in registers (packed f32x2 k-pairs). h staged in
// SMEM, double-buffered; per-step exchange via cp.async.bulk.shared::cluster
// into every peer's next-buffer with mbarrier complete_tx (4096 B per phase).
// ---------------------------------------------------------------------------
__global__ __launch_bounds__(512, 1) __cluster_dims__(8, 1, 1)
void scan_kernel(const float* __restrict__ Whh)
{
    __shared__ float hs[2][2][HID];            // [buf][batch][k]
    __shared__ float outs[2][64];              // [batch][il] my output slice
    __shared__ float part[8][64][2];           // [kg][il][b] k-split partials
    __shared__ __align__(8) ull mbar[2];

    const int tid = threadIdx.x;
    const int w = tid >> 5, l = tid & 31;
    const int kg = w >> 1;                     // 0..7, K chunk of 64
    const int il = ((w & 1) << 5) | l;         // 0..63 local hidden row

    unsigned rank;
    asm("mov.u32 %0, %%cluster_ctarank;" : "=r"(rank));
    const int b0 = (int)(blockIdx.x >> 3) * 2; // batch base for this cluster
    const int i0 = (int)rank * 64;             // hidden base for this CTA

    // Weights: rows i0+il, cols [kg*64, kg*64+64), packed as 32 f32x2 pairs.
    ull wp[32];
    {
        const float* wrow = Whh + (size_t)(i0 + il) * HID + kg * 64;
#pragma unroll
        for (int j = 0; j < 16; j++) {
            ulonglong2 v = *(const ulonglong2*)(wrow + j * 4);
            wp[2 * j] = v.x; wp[2 * j + 1] = v.y;
        }
    }

    uint32_t mb[2];
    mb[0] = (uint32_t)__cvta_generic_to_shared(&mbar[0]);
    mb[1] = (uint32_t)__cvta_generic_to_shared(&mbar[1]);

    if (tid == 0) {
        asm volatile("mbarrier.init.shared.b64 [%0], %1;" :: "r"(mb[0]), "r"(1u) : "memory");
        asm volatile("mbarrier.init.shared.b64 [%0], %1;" :: "r"(mb[1]), "r"(1u) : "memory");
    }
    for (int i = tid; i < 2 * HID; i += 512) ((float*)hs[0])[i] = 0.f;   // h(0)=0
    __syncthreads();
    asm volatile("barrier.cluster.arrive.aligned;" ::: "memory");
    asm volatile("barrier.cluster.wait.aligned;" ::: "memory");

    int ph0 = 0, ph1 = 0;
    const int rb = tid & 1, ril = tid >> 1;    // reduce role (tid < 128)

    float xp_cur = 0.f;
    if (tid < 128)
        xp_cur = __ldcg(&g_xproj[((size_t)0 * BATCH + b0 + rb) * HID + i0 + ril]);

    for (int s = 0; s < SEQ; s++) {
        const int cur = s & 1, nxt = cur ^ 1;
        const uint32_t mbn = (nxt == 0) ? mb[0] : mb[1];

        // prefetch next step's xproj slice (hidden behind compute)
        float xp_nextv = 0.f;
        if (tid < 128) {
            int sn = (s + 1 < SEQ) ? (s + 1) : s;
            xp_nextv = __ldcg(&g_xproj[((size_t)sn * BATCH + b0 + rb) * HID + i0 + ril]);
        }

        // matvec partial: acc_b = sum over my 64-K chunk of W[il][k]*h[k][b]
        ull a0 = 0ull, a1 = 0ull;
        const ulonglong2* h0 = (const ulonglong2*)&hs[cur][0][kg * 64];
        const ulonglong2* h1 = (const ulonglong2*)&hs[cur][1][kg * 64];
#pragma unroll
        for (int j = 0; j < 16; j++) {
            ulonglong2 hb0 = h0[j];
            ulonglong2 hb1 = h1[j];
            ffma2(a0, wp[2 * j],     hb0.x);
            ffma2(a0, wp[2 * j + 1], hb0.y);
            ffma2(a1, wp[2 * j],     hb1.x);
            ffma2(a1, wp[2 * j + 1], hb1.y);
        }
        float2 u0 = unpk(a0), u1 = unpk(a1);
        *(float2*)&part[kg][il][0] = make_float2(u0.x + u0.y, u1.x + u1.y);
        __syncthreads();

        if (tid < 128) {
            float sum = xp_cur;
#pragma unroll
            for (int g = 0; g < 8; g++) sum += part[g][ril][rb];
            outs[rb][ril] = tanhf(sum);
        }
        __syncthreads();

        if (tid == 0) {
            asm volatile("fence.proxy.async.shared::cta;" ::: "memory");
            asm volatile("mbarrier.arrive.expect_tx.shared::cta.b64 _, [%0], %1;"
                         :: "r"(mbn), "r"(4096u) : "memory");
            uint32_t src0 = (uint32_t)__cvta_generic_to_shared(&outs[0][0]);
            uint32_t src1 = (uint32_t)__cvta_generic_to_shared(&outs[1][0]);
            uint32_t d0   = (uint32_t)__cvta_generic_to_shared(&hs[nxt][0][i0]);
            uint32_t d1   = (uint32_t)__cvta_generic_to_shared(&hs[nxt][1][i0]);
#pragma unroll
            for (int p = 0; p < 8; p++) {
                uint32_t rd0, rd1, rmb;
                asm("mapa.shared::cluster.u32 %0, %1, %2;" : "=r"(rd0) : "r"(d0), "r"(p));
                asm("mapa.shared::cluster.u32 %0, %1, %2;" : "=r"(rd1) : "r"(d1), "r"(p));
                asm("mapa.shared::cluster.u32 %0, %1, %2;" : "=r"(rmb) : "r"(mbn), "r"(p));
                asm volatile(
                    "cp.async.bulk.shared::cluster.shared::cta.mbarrier::complete_tx::bytes [%0], [%1], %2, [%3];"
                    :: "r"(rd0), "r"(src0), "r"(256u), "r"(rmb) : "memory");
                asm volatile(
                    "cp.async.bulk.shared::cluster.shared::cta.mbarrier::complete_tx::bytes [%0], [%1], %2, [%3];"
                    :: "r"(rd1), "r"(src1), "r"(256u), "r"(rmb) : "memory");
            }
        }

        // wait for the full next-h buffer (all 8 slices delivered)
        {
            uint32_t phase = (uint32_t)((nxt == 0) ? ph0 : ph1);
            uint32_t done;
            asm volatile(
                "{\n\t.reg .pred p;\n\t"
                "mbarrier.try_wait.parity.acquire.cta.shared::cta.b64 p, [%1], %2;\n\t"
                "selp.b32 %0, 1, 0, p;\n\t}"
                : "=r"(done) : "r"(mbn), "r"(phase) : "memory");
            if (!done) {
                asm volatile(
                    "{\n\t.reg .pred P1;\n\t"
                    "W%=:\n\t"
                    "mbarrier.try_wait.parity.acquire.cta.shared::cta.b64 P1, [%0], %1, 0x989680;\n\t"
                    "@P1 bra.uni D%=;\n\t"
                    "bra.uni W%=;\n\t"
                    "D%=:\n\t}"
                    :: "r"(mbn), "r"(phase) : "memory");
            }
            if (nxt == 0) ph0 ^= 1; else ph1 ^= 1;
        }
        xp_cur = xp_nextv;
    }

    // outs still holds this CTA's slice of h(SEQ)
    if (tid < 128)
        g_hfin[(b0 + rb) * HID + i0 + ril] = outs[rb][ril];
}

// ---------------------------------------------------------------------------
// Kernel 3: out = h_final @ W_fc^T + b_fc. 512 blocks for occupancy.
// ---------------------------------------------------------------------------
__global__ __launch_bounds__(256) void fc_kernel(
    const float* __restrict__ Wfc, const float* __restrict__ bfc,
    float* __restrict__ out)
{
    __shared__ float hsm[HID];
    const int b = blockIdx.x;
    const int o0 = blockIdx.y * 32;
    const int tid = threadIdx.x;
    for (int i = tid; i < HID; i += 256) hsm[i] = g_hfin[b * HID + i];
    __syncthreads();
    const int w = tid >> 5, l = tid & 31;
#pragma unroll
    for (int oi = 0; oi < 4; oi++) {
        int o = o0 + w * 4 + oi;
        const float* wr = Wfc + (size_t)o * HID;
        float sum = 0.f;
#pragma unroll
        for (int j = 0; j < HID / 32; j++)
            sum = fmaf(hsm[j * 32 + l], wr[j * 32 + l], sum);
#pragma unroll
        for (int off = 16; off > 0; off >>= 1)
            sum += __shfl_down_sync(0xffffffffu, sum, off);
        if (l == 0) out[b * HID + o] = sum + bfc[o];
    }
}

// ---------------------------------------------------------------------------
extern "C" void kernel_launch(void* const* d_in, const int* in_sizes, int n_in,
                              void* d_out, int out_size)
{
    const float* x   = (const float*)d_in[0];
    const float* Wxh = (const float*)d_in[1];
    const float* bxh = (const float*)d_in[2];
    const float* Whh = (const float*)d_in[3];
    const float* bhh = (const float*)d_in[4];
    const float* bh  = (const float*)d_in[5];
    const float* Wfc = (const float*)d_in[6];
    const float* bfc = (const float*)d_in[7];
    float* out = (float*)d_out;

    xproj_gemm<<<dim3((BATCH * SEQ) / 128, HID / 128), 256>>>(x, Wxh, bxh, bhh, bh);
    scan_kernel<<<128, 512>>>(Whh);
    fc_kernel<<<dim3(BATCH, 16), 256>>>(Wfc, bfc, out);
}

// round 3
// speedup vs baseline: 1.4245x; 1.0627x over previous
#include <cuda_runtime.h>
#include <math.h>
#include <stdint.h>

#define BATCH 32
#define SEQ   2048
#define HID   512

typedef unsigned long long ull;

// Scratch (static device globals: allocation-free)
__device__ float g_xproj[SEQ * BATCH * HID];   // [s][b][h] layout
__device__ float g_hfin[BATCH * HID];          // final hidden state

// ---------------------------------------------------------------------------
// packed f32x2 helpers (FFMA2 only reachable via PTX)
// ---------------------------------------------------------------------------
__device__ __forceinline__ void ffma2(ull& acc, ull a, ull b) {
    asm("fma.rn.f32x2 %0, %1, %2, %0;" : "+l"(acc) : "l"(a), "l"(b));
}
__device__ __forceinline__ ull dup2(float v) {
    ull r; asm("mov.b64 %0, {%1, %1};" : "=l"(r) : "f"(v)); return r;
}
__device__ __forceinline__ float2 unpk(ull v) {
    float2 r; asm("mov.b64 {%0, %1}, %2;" : "=f"(r.x), "=f"(r.y) : "l"(v)); return r;
}

// ---------------------------------------------------------------------------
// Kernel 1: xproj = x @ W_xh^T + (b_xh + b_hh + b_h), written as [s][b][h]
// 128x128 block / 8x8 thread tile, packed FFMA2, register double-buffering.
// grid.x = n-tile (fast) so consecutive CTAs reuse the same X rows in L2.
// ---------------------------------------------------------------------------
__global__ __launch_bounds__(256, 2) void xproj_gemm(
    const float* __restrict__ X,
    const float* __restrict__ Wxh,
    const float* __restrict__ bxh,
    const float* __restrict__ bhh,
    const float* __restrict__ bh)
{
    __shared__ float As[8][128];
    __shared__ float Bs[8][128];
    const int K = HID;
    const int n0 = blockIdx.x * 128;
    const int m0 = blockIdx.y * 128;
    const int tid = threadIdx.x;

    const int lr = tid >> 1;
    const int lc = (tid & 1) << 2;
    const int ca = (tid & 15) << 2;
    const int ra = (tid >> 4) << 2;

    ull acc[8][4];
#pragma unroll
    for (int i = 0; i < 8; i++)
#pragma unroll
        for (int j = 0; j < 4; j++) acc[i][j] = 0ull;

    const float* Aptr = X   + (size_t)(m0 + lr) * K + lc;
    const float* Bptr = Wxh + (size_t)(n0 + lr) * K + lc;

    float4 a4 = *(const float4*)(Aptr);
    float4 b4 = *(const float4*)(Bptr);

    for (int k0 = 0; k0 < K; k0 += 8) {
        As[lc + 0][lr] = a4.x; As[lc + 1][lr] = a4.y;
        As[lc + 2][lr] = a4.z; As[lc + 3][lr] = a4.w;
        Bs[lc + 0][lr] = b4.x; Bs[lc + 1][lr] = b4.y;
        Bs[lc + 2][lr] = b4.z; Bs[lc + 3][lr] = b4.w;
        __syncthreads();
        if (k0 + 8 < K) {                     // prefetch next stage (hidden)
            a4 = *(const float4*)(Aptr + k0 + 8);
            b4 = *(const float4*)(Bptr + k0 + 8);
        }
#pragma unroll
        for (int k = 0; k < 8; k++) {
            float am[8];
            *(float4*)&am[0] = *(const float4*)&As[k][ra];
            *(float4*)&am[4] = *(const float4*)&As[k][ra + 64];
            ulonglong2 b01 = *(const ulonglong2*)&Bs[k][ca];
            ulonglong2 b23 = *(const ulonglong2*)&Bs[k][ca + 64];
#pragma unroll
            for (int i = 0; i < 8; i++) {
                ull ad = dup2(am[i]);
                ffma2(acc[i][0], ad, b01.x);
                ffma2(acc[i][1], ad, b01.y);
                ffma2(acc[i][2], ad, b23.x);
                ffma2(acc[i][3], ad, b23.y);
            }
        }
        __syncthreads();
    }

    float biasv[8];
#pragma unroll
    for (int j = 0; j < 8; j++) {
        int n = n0 + ((j < 4) ? (ca + j) : (64 + ca + j - 4));
        biasv[j] = bxh[n] + bhh[n] + bh[n];
    }

#pragma unroll
    for (int i = 0; i < 8; i++) {
        int m = m0 + ((i < 4) ? (ra + i) : (64 + ra + i - 4));
        int b = m >> 11;
        int s = m & (SEQ - 1);
        float* outr = &g_xproj[((size_t)s * BATCH + b) * HID + n0];
        float2 p0 = unpk(acc[i][0]);
        float2 p1 = unpk(acc[i][1]);
        float2 p2 = unpk(acc[i][2]);
        float2 p3 = unpk(acc[i][3]);
        float4 v0, v1;
        v0.x = p0.x + biasv[0]; v0.y = p0.y + biasv[1];
        v0.z = p1.x + biasv[2]; v0.w = p1.y + biasv[3];
        v1.x = p2.x + biasv[4]; v1.y = p2.y + biasv[5];
        v1.z = p3.x + biasv[6]; v1.w = p3.y + biasv[7];
        *(float4*)&outr[ca]      = v0;
        *(float4*)&outr[64 + ca] = v1;
    }
}

// ---------------------------------------------------------------------------
// Kernel 2: persistent recurrent scan over CGA clusters.
// 16 clusters x 8 CTAs. Cluster = 2 batches; CTA rank r = hidden rows
// [r*64, r*64+64). Weights in registers (packed f32x2). h double-buffered in
// SMEM; exchange via direct st.shared::cluster remote stores (per-thread, to
// all 8 peers); ordering via split cluster barrier (arrive at step end has
// release semantics over the remote stores; wait at next step top acquires).
// ---------------------------------------------------------------------------
__global__ __launch_bounds__(512, 1) __cluster_dims__(8, 1, 1)
void scan_kernel(const float* __restrict__ Whh)
{
    __shared__ float hs[2][2][HID];            // [buf][batch][k]  8KB
    __shared__ float part[8][2][65];           // [kg][batch][il]  pad->cf

    const int tid = threadIdx.x;
    const int w = tid >> 5, l = tid & 31;
    const int kg = w >> 1;                     // 0..7, K chunk of 64
    const int il = ((w & 1) << 5) | l;         // 0..63 local hidden row

    unsigned rank;
    asm("mov.u32 %0, %%cluster_ctarank;" : "=r"(rank));
    const int b0 = (int)(blockIdx.x >> 3) * 2; // batch base for this cluster
    const int i0 = (int)rank * 64;             // hidden base for this CTA

    // Weights: rows i0+il, cols [kg*64, kg*64+64), packed as 32 f32x2 pairs.
    ull wp[32];
    {
        const float* wrow = Whh + (size_t)(i0 + il) * HID + kg * 64;
#pragma unroll
        for (int j = 0; j < 16; j++) {
            ulonglong2 v = *(const ulonglong2*)(wrow + j * 4);
            wp[2 * j] = v.x; wp[2 * j + 1] = v.y;
        }
    }

    // Reduce/store roles (tid < 128): rb = batch, ril = local hidden row.
    const int rb  = (tid >> 6) & 1;
    const int ril = tid & 63;

    // Remote store bases: peer p's hs[] base in shared::cluster space.
    uint32_t hbase = (uint32_t)__cvta_generic_to_shared(&hs[0][0][0]);
    uint32_t rbase[8];
#pragma unroll
    for (int p = 0; p < 8; p++)
        asm("mapa.shared::cluster.u32 %0, %1, %2;" : "=r"(rbase[p]) : "r"(hbase), "r"(p));
    const uint32_t soff = (uint32_t)((rb * HID + i0 + ril) * 4);

    // h(0) = 0 locally (each CTA zeroes its own full buffer 0)
    for (int i = tid; i < 2 * HID; i += 512) ((float*)hs[0])[i] = 0.f;
    __syncthreads();
    asm volatile("barrier.cluster.arrive.aligned;" ::: "memory");   // arrive #0

    float xp_cur = 0.f;
    bool prod = (tid < 128);
    if (prod)
        xp_cur = __ldcg(&g_xproj[((size_t)0 * BATCH + b0 + rb) * HID + i0 + ril]);

    for (int s = 0; s < SEQ; s++) {
        const int cur = s & 1, nxt = cur ^ 1;

        asm volatile("barrier.cluster.wait.aligned;" ::: "memory"); // wait #s

        // prefetch next step's xproj slice (consumed next iteration)
        float xp_nextv = 0.f;
        if (prod) {
            int sn = (s + 1 < SEQ) ? (s + 1) : s;
            xp_nextv = __ldcg(&g_xproj[((size_t)sn * BATCH + b0 + rb) * HID + i0 + ril]);
        }

        // matvec partial over my 64-wide K chunk for both batches
        ull a0 = 0ull, a1 = 0ull;
        const ulonglong2* h0 = (const ulonglong2*)&hs[cur][0][kg * 64];
        const ulonglong2* h1 = (const ulonglong2*)&hs[cur][1][kg * 64];
#pragma unroll
        for (int j = 0; j < 16; j++) {
            ulonglong2 hb0 = h0[j];
            ulonglong2 hb1 = h1[j];
            ffma2(a0, wp[2 * j],     hb0.x);
            ffma2(a0, wp[2 * j + 1], hb0.y);
            ffma2(a1, wp[2 * j],     hb1.x);
            ffma2(a1, wp[2 * j + 1], hb1.y);
        }
        float2 u0 = unpk(a0), u1 = unpk(a1);
        part[kg][0][il] = u0.x + u0.y;
        part[kg][1][il] = u1.x + u1.y;
        __syncthreads();

        if (prod) {
            float sum = xp_cur;
#pragma unroll
            for (int g = 0; g < 8; g++) sum += part[g][rb][ril];
            float v = tanhf(sum);
            const uint32_t boff = (uint32_t)(nxt << 12) + soff;
#pragma unroll
            for (int p = 0; p < 8; p++) {
                asm volatile("st.shared::cluster.f32 [%0], %1;"
                             :: "r"(rbase[p] + boff), "f"(v) : "memory");
            }
        }

        asm volatile("barrier.cluster.arrive.aligned;" ::: "memory"); // arrive #s+1
        xp_cur = xp_nextv;
    }

    asm volatile("barrier.cluster.wait.aligned;" ::: "memory");       // wait #SEQ

    // hs[0] holds h(SEQ); each CTA writes its own slice.
    if (prod)
        g_hfin[(b0 + rb) * HID + i0 + ril] = hs[0][rb][i0 + ril];
}

// ---------------------------------------------------------------------------
// Kernel 3: out = h_final @ W_fc^T + b_fc.
// ---------------------------------------------------------------------------
__global__ __launch_bounds__(256) void fc_kernel(
    const float* __restrict__ Wfc, const float* __restrict__ bfc,
    float* __restrict__ out)
{
    __shared__ float hsm[HID];
    const int b = blockIdx.x;
    const int o0 = blockIdx.y * 32;
    const int tid = threadIdx.x;
    for (int i = tid; i < HID; i += 256) hsm[i] = g_hfin[b * HID + i];
    __syncthreads();
    const int w = tid >> 5, l = tid & 31;
#pragma unroll
    for (int oi = 0; oi < 4; oi++) {
        int o = o0 + w * 4 + oi;
        const float* wr = Wfc + (size_t)o * HID;
        float sum = 0.f;
#pragma unroll
        for (int j = 0; j < HID / 32; j++)
            sum = fmaf(hsm[j * 32 + l], wr[j * 32 + l], sum);
#pragma unroll
        for (int off = 16; off > 0; off >>= 1)
            sum += __shfl_down_sync(0xffffffffu, sum, off);
        if (l == 0) out[b * HID + o] = sum + bfc[o];
    }
}

// ---------------------------------------------------------------------------
extern "C" void kernel_launch(void* const* d_in, const int* in_sizes, int n_in,
                              void* d_out, int out_size)
{
    const float* x   = (const float*)d_in[0];
    const float* Wxh = (const float*)d_in[1];
    const float* bxh = (const float*)d_in[2];
    const float* Whh = (const float*)d_in[3];
    const float* bhh = (const float*)d_in[4];
    const float* bh  = (const float*)d_in[5];
    const float* Wfc = (const float*)d_in[6];
    const float* bfc = (const float*)d_in[7];
    float* out = (float*)d_out;

    xproj_gemm<<<dim3(HID / 128, (BATCH * SEQ) / 128), 256>>>(x, Wxh, bxh, bhh, bh);
    scan_kernel<<<128, 512>>>(Whh);
    fc_kernel<<<dim3(BATCH, 16), 256>>>(Wfc, bfc, out);
}